// round 14
// baseline (speedup 1.0000x reference)
#include <cuda_runtime.h>
#include <cuda_bf16.h>
#include <cuda_fp16.h>
#include <cstdint>

// Problem constants (shapes fixed by the dataset)
#define NMAX 50048
#define NPAD 50176                 // 49 * 1024, for the block scan
#define EMAX 800000
#define DIM  128
#define NHEADS 8
#define HDIM 16

// ---------------- scratch (device globals; no allocation allowed) -------------
__device__ __half  g_qh[NMAX * DIM];
__device__ __half  g_kh[NMAX * DIM];
__device__ __half  g_vh[NMAX * DIM];
// CSR-by-dst build
__device__ int g_deg[NPAD];
__device__ int g_off[NPAD];
__device__ int g_bsum[64];
__device__ int g_esrc[EMAX];
// bf16 weights (hi / lo split for the precision-critical paths)
__device__ __nv_bfloat16 g_Wqh[DIM * DIM];
__device__ __nv_bfloat16 g_Wkh[DIM * DIM];
__device__ __nv_bfloat16 g_Wvh[DIM * DIM];
__device__ __nv_bfloat16 g_Wvl[DIM * DIM];
__device__ __nv_bfloat16 g_Woh[DIM * DIM];
__device__ __nv_bfloat16 g_Wol[DIM * DIM];

// ---------------- helpers ------------------------------------------------------
__device__ __forceinline__ uint32_t smem_u32(const void* p) {
    uint32_t a;
    asm("{ .reg .u64 t; cvta.to.shared.u64 t, %1; cvt.u32.u64 %0, t; }"
        : "=r"(a) : "l"(p));
    return a;
}

// Swizzled byte offset in a [128 rows x 128 bf16] tile (XOR-16B-chunk swizzle).
__device__ __forceinline__ uint32_t toff(int r, int k) {
    return (uint32_t)((r << 8) + ((((k >> 3) ^ (r & 7))) << 4) + ((k & 7) << 1));
}

__device__ __forceinline__ void ldsm4(uint32_t addr, uint32_t* r) {
    asm volatile("ldmatrix.sync.aligned.m8n8.x4.shared.b16 {%0,%1,%2,%3}, [%4];"
                 : "=r"(r[0]), "=r"(r[1]), "=r"(r[2]), "=r"(r[3]) : "r"(addr));
}

__device__ __forceinline__ void mma16816(float* c, const uint32_t* a,
                                         const uint32_t* b) {
    asm volatile(
        "mma.sync.aligned.m16n8k16.row.col.f32.bf16.bf16.f32 "
        "{%0,%1,%2,%3}, {%4,%5,%6,%7}, {%8,%9}, {%0,%1,%2,%3};"
        : "+f"(c[0]), "+f"(c[1]), "+f"(c[2]), "+f"(c[3])
        : "r"(a[0]), "r"(a[1]), "r"(a[2]), "r"(a[3]), "r"(b[0]), "r"(b[1]));
}

__device__ __forceinline__ void split8(const float* x, uint4& uh, uint4& ul) {
    __nv_bfloat162* ph = (__nv_bfloat162*)&uh;
    __nv_bfloat162* pl = (__nv_bfloat162*)&ul;
    #pragma unroll
    for (int i = 0; i < 4; i++) {
        __nv_bfloat16 h0 = __float2bfloat16(x[2 * i]);
        __nv_bfloat16 h1 = __float2bfloat16(x[2 * i + 1]);
        ph[i] = __halves2bfloat162(h0, h1);
        pl[i] = __floats2bfloat162_rn(x[2 * i]     - __bfloat162float(h0),
                                      x[2 * i + 1] - __bfloat162float(h1));
    }
}

__device__ __forceinline__ void split4(const float* x, uint2& uh, uint2& ul) {
    __nv_bfloat162* ph = (__nv_bfloat162*)&uh;
    __nv_bfloat162* pl = (__nv_bfloat162*)&ul;
    #pragma unroll
    for (int i = 0; i < 2; i++) {
        __nv_bfloat16 h0 = __float2bfloat16(x[2 * i]);
        __nv_bfloat16 h1 = __float2bfloat16(x[2 * i + 1]);
        ph[i] = __halves2bfloat162(h0, h1);
        pl[i] = __floats2bfloat162_rn(x[2 * i]     - __bfloat162float(h0),
                                      x[2 * i + 1] - __bfloat162float(h1));
    }
}

// 128x128x128 GEMM tile: acc += Ahi*Bhi (+ Alo*Bhi if ALO) (+ Ahi*Blo if BLO).
template <bool ALO, bool BLO>
__device__ __forceinline__ void gemm128(uint32_t sb, int a_hi, int a_lo,
                                        int b_hi, int b_lo,
                                        float acc[2][4][4],
                                        int wm, int wn, int lane) {
    int a_row = (lane & 7) + ((lane >> 3) & 1) * 8;
    int a_k   = ((lane >> 4) & 1) * 8;
    int b_row = ((lane >> 4) & 1) * 8 + (lane & 7);
    int b_k   = ((lane >> 3) & 1) * 8;

    #pragma unroll 1
    for (int k0 = 0; k0 < 8; k0++) {
        int kb = k0 * 16;
        uint32_t ah[2][4], al[2][4];
        #pragma unroll
        for (int mi = 0; mi < 2; mi++) {
            int row = wm * 32 + mi * 16 + a_row;
            ldsm4(sb + a_hi + toff(row, kb + a_k), ah[mi]);
            if (ALO) ldsm4(sb + a_lo + toff(row, kb + a_k), al[mi]);
        }
        uint32_t bh[2][4], bl[2][4];
        #pragma unroll
        for (int pr = 0; pr < 2; pr++) {
            int row = wn * 32 + pr * 16 + b_row;
            ldsm4(sb + b_hi + toff(row, kb + b_k), bh[pr]);
            if (BLO) ldsm4(sb + b_lo + toff(row, kb + b_k), bl[pr]);
        }
        #pragma unroll
        for (int mi = 0; mi < 2; mi++) {
            #pragma unroll
            for (int nt = 0; nt < 4; nt++) {
                uint32_t* b = &bh[nt >> 1][(nt & 1) * 2];
                mma16816(acc[mi][nt], ah[mi], b);
                if (ALO) mma16816(acc[mi][nt], al[mi], b);
                if (BLO) mma16816(acc[mi][nt], ah[mi], &bl[nt >> 1][(nt & 1) * 2]);
            }
        }
    }
}

// ---------------- K0: setup (zero deg + weight prep fused) ---------------------
__global__ void setup_kernel(const float* __restrict__ Wq, const float* __restrict__ Wk,
                             const float* __restrict__ Wv, const float* __restrict__ Wo) {
    int i = blockIdx.x * blockDim.x + threadIdx.x;
    if (i < NPAD) g_deg[i] = 0;
    if (i < DIM * DIM) {
        g_Wqh[i] = __float2bfloat16(Wq[i]);
        g_Wkh[i] = __float2bfloat16(Wk[i]);
        float v = Wv[i];
        __nv_bfloat16 vh = __float2bfloat16(v);
        g_Wvh[i] = vh;
        g_Wvl[i] = __float2bfloat16(v - __bfloat162float(vh));
        float o = Wo[i];
        __nv_bfloat16 oh = __float2bfloat16(o);
        g_Woh[i] = oh;
        g_Wol[i] = __float2bfloat16(o - __bfloat162float(oh));
    }
}

// ---------------- scan (shuffle-based) + scatter -------------------------------
__global__ void scanA_kernel() {               // 49 blocks x 1024
    __shared__ int wsum[32];
    int t = threadIdx.x;
    int lane = t & 31, w = t >> 5;
    int i = blockIdx.x * 1024 + t;
    int v = g_deg[i];
    int x = v;
    #pragma unroll
    for (int ofs = 1; ofs < 32; ofs <<= 1) {
        int y = __shfl_up_sync(0xffffffffu, x, ofs);
        if (lane >= ofs) x += y;
    }
    if (lane == 31) wsum[w] = x;
    __syncthreads();
    if (w == 0) {
        int s = wsum[lane];
        #pragma unroll
        for (int ofs = 1; ofs < 32; ofs <<= 1) {
            int y = __shfl_up_sync(0xffffffffu, s, ofs);
            if (lane >= ofs) s += y;
        }
        wsum[lane] = s;
    }
    __syncthreads();
    int bp = (w > 0) ? wsum[w - 1] : 0;
    g_off[i] = bp + x - v;                     // exclusive within block
    if (t == 1023) g_bsum[blockIdx.x] = bp + x;
}

__global__ void scanBC_kernel() {              // 49 blocks x 1024
    __shared__ int pref;
    int t = threadIdx.x;
    if (t == 0) {
        int s = 0;
        for (int j = 0; j < blockIdx.x; j++) s += g_bsum[j];
        pref = s;
    }
    __syncthreads();
    g_off[blockIdx.x * 1024 + t] += pref;
}

// Destructive scatter: g_off[d] becomes the END offset; beg = off - deg.
__global__ void scatter_kernel(const int* __restrict__ src,
                               const int* __restrict__ dst, int E) {
    int e = blockIdx.x * blockDim.x + threadIdx.x;
    if (e < E) {
        int pos = atomicAdd(&g_off[dst[e]], 1);
        g_esrc[pos] = src[e];
    }
}

// ---------------- K1: QKV projection via mma.sync bf16 (+ fused histogram) -----
#define QS_AHI  2048
#define QS_ALO  (QS_AHI + 32768)
#define QS_WQ   (QS_ALO + 32768)
#define QS_WK   (QS_WQ + 32768)
#define QS_WVH  (QS_WK + 32768)
#define QS_WVL  (QS_WVH + 32768)
#define QS_TOTAL (QS_WVL + 32768)          // 198656 bytes

__global__ __launch_bounds__(512, 1)
void qkv_mma_kernel(const float* __restrict__ h,
                    const float* __restrict__ bq, const float* __restrict__ bk,
                    const float* __restrict__ bv,
                    const int* __restrict__ dst, int E, int n, int ntiles) {
    extern __shared__ char smem[];
    uint32_t sb = smem_u32(smem);
    int tid = threadIdx.x, wid = tid >> 5, lane = tid & 31;
    int wm = wid & 3, wn = wid >> 2;
    int g = lane >> 2, t = lane & 3;

    float* bias_s = (float*)smem;
    for (int i = tid; i < 384; i += 512)
        bias_s[i] = (i < 128) ? bq[i] : (i < 256) ? bk[i - 128] : bv[i - 256];

    for (int c = tid; c < 2048; c += 512) {
        int r = c >> 4, k8 = (c & 15) << 3;
        uint32_t off = toff(r, k8);
        int gi = (r * DIM + k8) >> 3;
        *(uint4*)(smem + QS_WQ  + off) = ((const uint4*)g_Wqh)[gi];
        *(uint4*)(smem + QS_WK  + off) = ((const uint4*)g_Wkh)[gi];
        *(uint4*)(smem + QS_WVH + off) = ((const uint4*)g_Wvh)[gi];
        *(uint4*)(smem + QS_WVL + off) = ((const uint4*)g_Wvl)[gi];
    }

    // fused degree histogram (g_deg zeroed by setup_kernel)
    for (int e = blockIdx.x * 512 + tid; e < E; e += gridDim.x * 512)
        atomicAdd(&g_deg[dst[e]], 1);

    float xr[4][8];
    auto load_tile = [&](int tt) {
        int r0n = tt << 7;
        #pragma unroll
        for (int i = 0; i < 4; i++) {
            int c = tid + (i << 9);
            int r = c >> 4, k8 = (c & 15) << 3;
            int gr = r0n + r;
            if (gr < n) {
                float4 f0 = __ldg((const float4*)(h + (size_t)gr * DIM + k8));
                float4 f1 = __ldg((const float4*)(h + (size_t)gr * DIM + k8 + 4));
                xr[i][0] = f0.x; xr[i][1] = f0.y; xr[i][2] = f0.z; xr[i][3] = f0.w;
                xr[i][4] = f1.x; xr[i][5] = f1.y; xr[i][6] = f1.z; xr[i][7] = f1.w;
            } else {
                #pragma unroll
                for (int j = 0; j < 8; j++) xr[i][j] = 0.0f;
            }
        }
    };
    if (blockIdx.x < ntiles) load_tile(blockIdx.x);
    __syncthreads();

    for (int tile = blockIdx.x; tile < ntiles; tile += gridDim.x) {
        int r0 = tile << 7;

        #pragma unroll
        for (int i = 0; i < 4; i++) {
            int c = tid + (i << 9);
            int r = c >> 4, k8 = (c & 15) << 3;
            uint4 uh, ul;
            split8(xr[i], uh, ul);
            uint32_t off = toff(r, k8);
            *(uint4*)(smem + QS_AHI + off) = uh;
            *(uint4*)(smem + QS_ALO + off) = ul;
        }
        __syncthreads();

        int tn = tile + gridDim.x;
        if (tn < ntiles) load_tile(tn);        // hides under the GEMMs below

        // ---- q (1 pass) ----
        {
            float acc[2][4][4] = {};
            gemm128<false, false>(sb, QS_AHI, QS_ALO, QS_WQ, 0, acc, wm, wn, lane);
            #pragma unroll
            for (int mi = 0; mi < 2; mi++) {
                #pragma unroll
                for (int nt = 0; nt < 4; nt++) {
                    int col = wn * 32 + nt * 8 + 2 * t;
                    float b0 = bias_s[col], b1 = bias_s[col + 1];
                    int row = r0 + wm * 32 + mi * 16 + g;
                    if (row < n)
                        *(__half2*)(g_qh + (size_t)row * DIM + col) =
                            __floats2half2_rn(acc[mi][nt][0] + b0, acc[mi][nt][1] + b1);
                    if (row + 8 < n)
                        *(__half2*)(g_qh + (size_t)(row + 8) * DIM + col) =
                            __floats2half2_rn(acc[mi][nt][2] + b0, acc[mi][nt][3] + b1);
                }
            }
        }
        // ---- k (1 pass) ----
        {
            float acc[2][4][4] = {};
            gemm128<false, false>(sb, QS_AHI, QS_ALO, QS_WK, 0, acc, wm, wn, lane);
            #pragma unroll
            for (int mi = 0; mi < 2; mi++) {
                #pragma unroll
                for (int nt = 0; nt < 4; nt++) {
                    int col = wn * 32 + nt * 8 + 2 * t;
                    float b0 = bias_s[128 + col], b1 = bias_s[128 + col + 1];
                    int row = r0 + wm * 32 + mi * 16 + g;
                    if (row < n)
                        *(__half2*)(g_kh + (size_t)row * DIM + col) =
                            __floats2half2_rn(acc[mi][nt][0] + b0, acc[mi][nt][1] + b1);
                    if (row + 8 < n)
                        *(__half2*)(g_kh + (size_t)(row + 8) * DIM + col) =
                            __floats2half2_rn(acc[mi][nt][2] + b0, acc[mi][nt][3] + b1);
                }
            }
        }
        // ---- v (3-pass split) ----
        {
            float acc[2][4][4] = {};
            gemm128<true, true>(sb, QS_AHI, QS_ALO, QS_WVH, QS_WVL, acc, wm, wn, lane);
            #pragma unroll
            for (int mi = 0; mi < 2; mi++) {
                #pragma unroll
                for (int nt = 0; nt < 4; nt++) {
                    int col = wn * 32 + nt * 8 + 2 * t;
                    float b0 = bias_s[256 + col], b1 = bias_s[256 + col + 1];
                    int row = r0 + wm * 32 + mi * 16 + g;
                    if (row < n)
                        *(__half2*)(g_vh + (size_t)row * DIM + col) =
                            __floats2half2_rn(acc[mi][nt][0] + b0, acc[mi][nt][1] + b1);
                    if (row + 8 < n)
                        *(__half2*)(g_vh + (size_t)(row + 8) * DIM + col) =
                            __floats2half2_rn(acc[mi][nt][2] + b0, acc[mi][nt][3] + b1);
                }
            }
        }
        __syncthreads();
    }
}

// ---------------- K2: fused gather + output projection -------------------------
// Per 128-node tile: 16 warps gather 8 nodes each (softmax-weighted v sums in
// registers), write normalized A directly into swizzled smem (bf16 hi/lo),
// then the whole CTA runs the 128x128x128 MMA epilogue. No g_agg round-trip.
#define FS_AHI  2048
#define FS_ALO  (FS_AHI + 32768)
#define FS_WH   (FS_ALO + 32768)
#define FS_WL   (FS_WH + 32768)
#define FS_TOTAL (FS_WL + 32768)           // 133120 bytes

__global__ __launch_bounds__(512, 1)
void fused_out_kernel(const float* __restrict__ bo, float* __restrict__ out,
                      int n, int ntiles) {
    extern __shared__ char smem[];
    uint32_t sb = smem_u32(smem);
    int tid = threadIdx.x, wid = tid >> 5, lane = tid & 31;
    int wm = wid & 3, wn = wid >> 2;
    int g = lane >> 2, t = lane & 3;

    float* bias_s = (float*)smem;
    for (int i = tid; i < 128; i += 512) bias_s[i] = bo[i];

    for (int c = tid; c < 2048; c += 512) {
        int r = c >> 4, k8 = (c & 15) << 3;
        uint32_t off = toff(r, k8);
        int gi = (r * DIM + k8) >> 3;
        *(uint4*)(smem + FS_WH + off) = ((const uint4*)g_Woh)[gi];
        *(uint4*)(smem + FS_WL + off) = ((const uint4*)g_Wol)[gi];
    }
    __syncthreads();

    for (int tile = blockIdx.x; tile < ntiles; tile += gridDim.x) {
        int r0 = tile << 7;

        // ---- gather phase: warp wid handles rows wid*8 .. wid*8+7 ----
        #pragma unroll 1
        for (int i = 0; i < 8; i++) {
            int row = wid * 8 + i;
            int node = r0 + row;
            float x[4] = {0.f, 0.f, 0.f, 0.f};
            if (node < n) {
                int end = g_off[node];              // destructive scatter: end
                int beg = end - g_deg[node];

                uint2 ku = __ldg(((const uint2*)g_kh) + (size_t)node * 32 + lane);
                float2 k01 = __half22float2(*(const __half2*)&ku.x);
                float2 k23 = __half22float2(*(const __half2*)&ku.y);

                float a0 = 0.f, a1 = 0.f, a2 = 0.f, a3 = 0.f;
                float dsum = 0.f;

                for (int base = beg; base < end; base += 32) {
                    int m = end - base;
                    if (m > 32) m = 32;
                    int sl = (base + lane < end) ? __ldg(&g_esrc[base + lane]) : 0;
                    #pragma unroll 2
                    for (int j = 0; j < m; j++) {
                        int s = __shfl_sync(0xffffffffu, sl, j);
                        uint2 qu = __ldg(((const uint2*)g_qh) + (size_t)s * 32 + lane);
                        uint2 vu = __ldg(((const uint2*)g_vh) + (size_t)s * 32 + lane);
                        float2 q01 = __half22float2(*(const __half2*)&qu.x);
                        float2 q23 = __half22float2(*(const __half2*)&qu.y);
                        float p = q01.x * k01.x + q01.y * k01.y +
                                  q23.x * k23.x + q23.y * k23.y;
                        p += __shfl_xor_sync(0xffffffffu, p, 1);
                        p += __shfl_xor_sync(0xffffffffu, p, 2);
                        float we = __expf(p * 0.25f);
                        float2 v01 = __half22float2(*(const __half2*)&vu.x);
                        float2 v23 = __half22float2(*(const __half2*)&vu.y);
                        a0 = fmaf(we, v01.x, a0);
                        a1 = fmaf(we, v01.y, a1);
                        a2 = fmaf(we, v23.x, a2);
                        a3 = fmaf(we, v23.y, a3);
                        dsum += we;
                    }
                }
                float inv = (dsum > 0.f) ? __frcp_rn(dsum) : 0.f;
                x[0] = a0 * inv; x[1] = a1 * inv; x[2] = a2 * inv; x[3] = a3 * inv;
            }
            uint2 uh, ul;
            split4(x, uh, ul);
            uint32_t off = toff(row, lane * 4);   // 8B-aligned slot per lane
            *(uint2*)(smem + FS_AHI + off) = uh;
            *(uint2*)(smem + FS_ALO + off) = ul;
        }
        __syncthreads();

        // ---- GEMM phase ----
        float acc[2][4][4] = {};
        gemm128<true, true>(sb, FS_AHI, FS_ALO, FS_WH, FS_WL, acc, wm, wn, lane);

        #pragma unroll
        for (int mi = 0; mi < 2; mi++) {
            #pragma unroll
            for (int nt = 0; nt < 4; nt++) {
                int col = wn * 32 + nt * 8 + 2 * t;
                float b0 = bias_s[col], b1 = bias_s[col + 1];
                int row = r0 + wm * 32 + mi * 16 + g;
                if (row < n) {
                    float2 f = {acc[mi][nt][0] + b0, acc[mi][nt][1] + b1};
                    *(float2*)(out + (size_t)row * DIM + col) = f;
                }
                if (row + 8 < n) {
                    float2 f = {acc[mi][nt][2] + b0, acc[mi][nt][3] + b1};
                    *(float2*)(out + (size_t)(row + 8) * DIM + col) = f;
                }
            }
        }
        __syncthreads();
    }
}

// ---------------- launch -------------------------------------------------------
extern "C" void kernel_launch(void* const* d_in, const int* in_sizes, int n_in,
                              void* d_out, int out_size) {
    const float* h   = (const float*)d_in[0];
    const int*   src = (const int*)d_in[1];
    const int*   dst = (const int*)d_in[2];
    const float* Wq  = (const float*)d_in[3];
    const float* bq  = (const float*)d_in[4];
    const float* Wk  = (const float*)d_in[5];
    const float* bk  = (const float*)d_in[6];
    const float* Wv  = (const float*)d_in[7];
    const float* bv  = (const float*)d_in[8];
    const float* Wo  = (const float*)d_in[9];
    const float* bo  = (const float*)d_in[10];
    float* out = (float*)d_out;

    int n = in_sizes[0] / DIM;
    int E = in_sizes[1];
    int ntiles = (n + 127) / 128;

    cudaFuncSetAttribute(qkv_mma_kernel,
                         cudaFuncAttributeMaxDynamicSharedMemorySize, QS_TOTAL);
    cudaFuncSetAttribute(fused_out_kernel,
                         cudaFuncAttributeMaxDynamicSharedMemorySize, FS_TOTAL);

    setup_kernel<<<(NPAD + 255) / 256, 256>>>(Wq, Wk, Wv, Wo);

    qkv_mma_kernel<<<148, 512, QS_TOTAL>>>(h, bq, bk, bv, dst, E, n, ntiles);

    scanA_kernel<<<NPAD / 1024, 1024>>>();
    scanBC_kernel<<<NPAD / 1024, 1024>>>();
    scatter_kernel<<<(E + 255) / 256, 256>>>(src, dst, E);

    fused_out_kernel<<<148, 512, FS_TOTAL>>>(bo, out, n, ntiles);
}

// round 15
// speedup vs baseline: 1.7787x; 1.7787x over previous
#include <cuda_runtime.h>
#include <cuda_bf16.h>
#include <cuda_fp16.h>
#include <cstdint>

// Problem constants (shapes fixed by the dataset)
#define NMAX 50048
#define NPAD 50176                 // 49 * 1024, for the block scan
#define EMAX 800000
#define DIM  128
#define NHEADS 8
#define HDIM 16

// ---------------- scratch (device globals; no allocation allowed) -------------
__device__ __half  g_qh[NMAX * DIM];
__device__ __half  g_kh[NMAX * DIM];
__device__ __half  g_vh[NMAX * DIM];
__device__ float   g_agg[NMAX * DIM];
__device__ float   g_denom[NMAX * NHEADS];
// CSR-by-dst build
__device__ int g_deg[NPAD];
__device__ int g_off[NPAD];        // within-block exclusive offsets (scanA), then += deg after scatter
__device__ int g_bsum[64];         // block totals -> exclusive block prefixes (scanB)
__device__ int g_esrc[EMAX];
// bf16 weights (hi / lo split for the precision-critical paths)
__device__ __nv_bfloat16 g_Wqh[DIM * DIM];
__device__ __nv_bfloat16 g_Wkh[DIM * DIM];
__device__ __nv_bfloat16 g_Wvh[DIM * DIM];
__device__ __nv_bfloat16 g_Wvl[DIM * DIM];
__device__ __nv_bfloat16 g_Woh[DIM * DIM];
__device__ __nv_bfloat16 g_Wol[DIM * DIM];

// ---------------- helpers ------------------------------------------------------
__device__ __forceinline__ uint32_t smem_u32(const void* p) {
    uint32_t a;
    asm("{ .reg .u64 t; cvta.to.shared.u64 t, %1; cvt.u32.u64 %0, t; }"
        : "=r"(a) : "l"(p));
    return a;
}

// Swizzled byte offset in a [128 rows x 128 bf16] tile (XOR-16B-chunk swizzle).
__device__ __forceinline__ uint32_t toff(int r, int k) {
    return (uint32_t)((r << 8) + ((((k >> 3) ^ (r & 7))) << 4) + ((k & 7) << 1));
}

__device__ __forceinline__ void ldsm4(uint32_t addr, uint32_t* r) {
    asm volatile("ldmatrix.sync.aligned.m8n8.x4.shared.b16 {%0,%1,%2,%3}, [%4];"
                 : "=r"(r[0]), "=r"(r[1]), "=r"(r[2]), "=r"(r[3]) : "r"(addr));
}

__device__ __forceinline__ void mma16816(float* c, const uint32_t* a,
                                         const uint32_t* b) {
    asm volatile(
        "mma.sync.aligned.m16n8k16.row.col.f32.bf16.bf16.f32 "
        "{%0,%1,%2,%3}, {%4,%5,%6,%7}, {%8,%9}, {%0,%1,%2,%3};"
        : "+f"(c[0]), "+f"(c[1]), "+f"(c[2]), "+f"(c[3])
        : "r"(a[0]), "r"(a[1]), "r"(a[2]), "r"(a[3]), "r"(b[0]), "r"(b[1]));
}

__device__ __forceinline__ void split8(const float* x, uint4& uh, uint4& ul) {
    __nv_bfloat162* ph = (__nv_bfloat162*)&uh;
    __nv_bfloat162* pl = (__nv_bfloat162*)&ul;
    #pragma unroll
    for (int i = 0; i < 4; i++) {
        __nv_bfloat16 h0 = __float2bfloat16(x[2 * i]);
        __nv_bfloat16 h1 = __float2bfloat16(x[2 * i + 1]);
        ph[i] = __halves2bfloat162(h0, h1);
        pl[i] = __floats2bfloat162_rn(x[2 * i]     - __bfloat162float(h0),
                                      x[2 * i + 1] - __bfloat162float(h1));
    }
}

// 128x128x128 GEMM tile: acc += Ahi*Bhi (+ Alo*Bhi if ALO) (+ Ahi*Blo if BLO).
template <bool ALO, bool BLO>
__device__ __forceinline__ void gemm128(uint32_t sb, int a_hi, int a_lo,
                                        int b_hi, int b_lo,
                                        float acc[2][4][4],
                                        int wm, int wn, int lane) {
    int a_row = (lane & 7) + ((lane >> 3) & 1) * 8;
    int a_k   = ((lane >> 4) & 1) * 8;
    int b_row = ((lane >> 4) & 1) * 8 + (lane & 7);
    int b_k   = ((lane >> 3) & 1) * 8;

    #pragma unroll 1
    for (int k0 = 0; k0 < 8; k0++) {
        int kb = k0 * 16;
        uint32_t ah[2][4], al[2][4];
        #pragma unroll
        for (int mi = 0; mi < 2; mi++) {
            int row = wm * 32 + mi * 16 + a_row;
            ldsm4(sb + a_hi + toff(row, kb + a_k), ah[mi]);
            if (ALO) ldsm4(sb + a_lo + toff(row, kb + a_k), al[mi]);
        }
        uint32_t bh[2][4], bl[2][4];
        #pragma unroll
        for (int pr = 0; pr < 2; pr++) {
            int row = wn * 32 + pr * 16 + b_row;
            ldsm4(sb + b_hi + toff(row, kb + b_k), bh[pr]);
            if (BLO) ldsm4(sb + b_lo + toff(row, kb + b_k), bl[pr]);
        }
        #pragma unroll
        for (int mi = 0; mi < 2; mi++) {
            #pragma unroll
            for (int nt = 0; nt < 4; nt++) {
                uint32_t* b = &bh[nt >> 1][(nt & 1) * 2];
                mma16816(acc[mi][nt], ah[mi], b);
                if (ALO) mma16816(acc[mi][nt], al[mi], b);
                if (BLO) mma16816(acc[mi][nt], ah[mi], &bl[nt >> 1][(nt & 1) * 2]);
            }
        }
    }
}

// ---------------- K0: setup (zero deg + weight prep fused) ---------------------
__global__ void setup_kernel(const float* __restrict__ Wq, const float* __restrict__ Wk,
                             const float* __restrict__ Wv, const float* __restrict__ Wo) {
    int i = blockIdx.x * blockDim.x + threadIdx.x;
    if (i < NPAD) g_deg[i] = 0;
    if (i < DIM * DIM) {
        g_Wqh[i] = __float2bfloat16(Wq[i]);
        g_Wkh[i] = __float2bfloat16(Wk[i]);
        float v = Wv[i];
        __nv_bfloat16 vh = __float2bfloat16(v);
        g_Wvh[i] = vh;
        g_Wvl[i] = __float2bfloat16(v - __bfloat162float(vh));
        float o = Wo[i];
        __nv_bfloat16 oh = __float2bfloat16(o);
        g_Woh[i] = oh;
        g_Wol[i] = __float2bfloat16(o - __bfloat162float(oh));
    }
}

// ---------------- scan (shuffle-based, block-local) -----------------------------
__global__ void scanA_kernel() {               // 49 blocks x 1024
    __shared__ int wsum[32];
    int t = threadIdx.x;
    int lane = t & 31, w = t >> 5;
    int i = blockIdx.x * 1024 + t;
    int v = g_deg[i];
    int x = v;
    #pragma unroll
    for (int ofs = 1; ofs < 32; ofs <<= 1) {
        int y = __shfl_up_sync(0xffffffffu, x, ofs);
        if (lane >= ofs) x += y;
    }
    if (lane == 31) wsum[w] = x;
    __syncthreads();
    if (w == 0) {
        int s = wsum[lane];
        #pragma unroll
        for (int ofs = 1; ofs < 32; ofs <<= 1) {
            int y = __shfl_up_sync(0xffffffffu, s, ofs);
            if (lane >= ofs) s += y;
        }
        wsum[lane] = s;
    }
    __syncthreads();
    int bp = (w > 0) ? wsum[w - 1] : 0;
    g_off[i] = bp + x - v;                     // exclusive WITHIN block
    if (t == 1023) g_bsum[blockIdx.x] = bp + x;
}

__global__ void scanB_kernel() {               // 1 block x 64: exclusive prefix of 49 totals
    int t = threadIdx.x;
    int lane = t & 31, w = t >> 5;
    __shared__ int sh[64];
    int v = (t < 49) ? g_bsum[t] : 0;
    int x = v;
    #pragma unroll
    for (int ofs = 1; ofs < 32; ofs <<= 1) {
        int y = __shfl_up_sync(0xffffffffu, x, ofs);
        if (lane >= ofs) x += y;
    }
    sh[t] = x;
    __syncthreads();
    int total0 = sh[31];                       // sum of first warp
    int res = x - v + ((w == 1) ? total0 : 0); // exclusive prefix
    if (t < 49) g_bsum[t] = res;
}

// Destructive scatter: global pos = block-prefix + within-block running offset.
__global__ void scatter_kernel(const int* __restrict__ src,
                               const int* __restrict__ dst, int E) {
    int e = blockIdx.x * blockDim.x + threadIdx.x;
    if (e < E) {
        int d = dst[e];
        int pos = g_bsum[d >> 10] + atomicAdd(&g_off[d], 1);
        g_esrc[pos] = src[e];
    }
}

// ---------------- K1: QKV projection via mma.sync bf16 (+ fused histogram) -----
#define QS_AHI  2048
#define QS_ALO  (QS_AHI + 32768)
#define QS_WQ   (QS_ALO + 32768)
#define QS_WK   (QS_WQ + 32768)
#define QS_WVH  (QS_WK + 32768)
#define QS_WVL  (QS_WVH + 32768)
#define QS_TOTAL (QS_WVL + 32768)          // 198656 bytes

__global__ __launch_bounds__(512, 1)
void qkv_mma_kernel(const float* __restrict__ h,
                    const float* __restrict__ bq, const float* __restrict__ bk,
                    const float* __restrict__ bv,
                    const int* __restrict__ dst, int E, int n, int ntiles) {
    extern __shared__ char smem[];
    uint32_t sb = smem_u32(smem);
    int tid = threadIdx.x, wid = tid >> 5, lane = tid & 31;
    int wm = wid & 3, wn = wid >> 2;
    int g = lane >> 2, t = lane & 3;

    float* bias_s = (float*)smem;
    for (int i = tid; i < 384; i += 512)
        bias_s[i] = (i < 128) ? bq[i] : (i < 256) ? bk[i - 128] : bv[i - 256];

    for (int c = tid; c < 2048; c += 512) {
        int r = c >> 4, k8 = (c & 15) << 3;
        uint32_t off = toff(r, k8);
        int gi = (r * DIM + k8) >> 3;
        *(uint4*)(smem + QS_WQ  + off) = ((const uint4*)g_Wqh)[gi];
        *(uint4*)(smem + QS_WK  + off) = ((const uint4*)g_Wkh)[gi];
        *(uint4*)(smem + QS_WVH + off) = ((const uint4*)g_Wvh)[gi];
        *(uint4*)(smem + QS_WVL + off) = ((const uint4*)g_Wvl)[gi];
    }

    // fused degree histogram (g_deg zeroed by setup_kernel)
    for (int e = blockIdx.x * 512 + tid; e < E; e += gridDim.x * 512)
        atomicAdd(&g_deg[dst[e]], 1);

    float xr[4][8];
    auto load_tile = [&](int tt) {
        int r0n = tt << 7;
        #pragma unroll
        for (int i = 0; i < 4; i++) {
            int c = tid + (i << 9);
            int r = c >> 4, k8 = (c & 15) << 3;
            int gr = r0n + r;
            if (gr < n) {
                float4 f0 = __ldg((const float4*)(h + (size_t)gr * DIM + k8));
                float4 f1 = __ldg((const float4*)(h + (size_t)gr * DIM + k8 + 4));
                xr[i][0] = f0.x; xr[i][1] = f0.y; xr[i][2] = f0.z; xr[i][3] = f0.w;
                xr[i][4] = f1.x; xr[i][5] = f1.y; xr[i][6] = f1.z; xr[i][7] = f1.w;
            } else {
                #pragma unroll
                for (int j = 0; j < 8; j++) xr[i][j] = 0.0f;
            }
        }
    };
    if (blockIdx.x < ntiles) load_tile(blockIdx.x);
    __syncthreads();

    for (int tile = blockIdx.x; tile < ntiles; tile += gridDim.x) {
        int r0 = tile << 7;

        #pragma unroll
        for (int i = 0; i < 4; i++) {
            int c = tid + (i << 9);
            int r = c >> 4, k8 = (c & 15) << 3;
            uint4 uh, ul;
            split8(xr[i], uh, ul);
            uint32_t off = toff(r, k8);
            *(uint4*)(smem + QS_AHI + off) = uh;
            *(uint4*)(smem + QS_ALO + off) = ul;
        }
        __syncthreads();

        int tn = tile + gridDim.x;
        if (tn < ntiles) load_tile(tn);        // hides under the GEMMs below

        // ---- q (1 pass) ----
        {
            float acc[2][4][4] = {};
            gemm128<false, false>(sb, QS_AHI, QS_ALO, QS_WQ, 0, acc, wm, wn, lane);
            #pragma unroll
            for (int mi = 0; mi < 2; mi++) {
                #pragma unroll
                for (int nt = 0; nt < 4; nt++) {
                    int col = wn * 32 + nt * 8 + 2 * t;
                    float b0 = bias_s[col], b1 = bias_s[col + 1];
                    int row = r0 + wm * 32 + mi * 16 + g;
                    if (row < n)
                        *(__half2*)(g_qh + (size_t)row * DIM + col) =
                            __floats2half2_rn(acc[mi][nt][0] + b0, acc[mi][nt][1] + b1);
                    if (row + 8 < n)
                        *(__half2*)(g_qh + (size_t)(row + 8) * DIM + col) =
                            __floats2half2_rn(acc[mi][nt][2] + b0, acc[mi][nt][3] + b1);
                }
            }
        }
        // ---- k (1 pass) ----
        {
            float acc[2][4][4] = {};
            gemm128<false, false>(sb, QS_AHI, QS_ALO, QS_WK, 0, acc, wm, wn, lane);
            #pragma unroll
            for (int mi = 0; mi < 2; mi++) {
                #pragma unroll
                for (int nt = 0; nt < 4; nt++) {
                    int col = wn * 32 + nt * 8 + 2 * t;
                    float b0 = bias_s[128 + col], b1 = bias_s[128 + col + 1];
                    int row = r0 + wm * 32 + mi * 16 + g;
                    if (row < n)
                        *(__half2*)(g_kh + (size_t)row * DIM + col) =
                            __floats2half2_rn(acc[mi][nt][0] + b0, acc[mi][nt][1] + b1);
                    if (row + 8 < n)
                        *(__half2*)(g_kh + (size_t)(row + 8) * DIM + col) =
                            __floats2half2_rn(acc[mi][nt][2] + b0, acc[mi][nt][3] + b1);
                }
            }
        }
        // ---- v (3-pass split) ----
        {
            float acc[2][4][4] = {};
            gemm128<true, true>(sb, QS_AHI, QS_ALO, QS_WVH, QS_WVL, acc, wm, wn, lane);
            #pragma unroll
            for (int mi = 0; mi < 2; mi++) {
                #pragma unroll
                for (int nt = 0; nt < 4; nt++) {
                    int col = wn * 32 + nt * 8 + 2 * t;
                    float b0 = bias_s[256 + col], b1 = bias_s[256 + col + 1];
                    int row = r0 + wm * 32 + mi * 16 + g;
                    if (row < n)
                        *(__half2*)(g_vh + (size_t)row * DIM + col) =
                            __floats2half2_rn(acc[mi][nt][0] + b0, acc[mi][nt][1] + b1);
                    if (row + 8 < n)
                        *(__half2*)(g_vh + (size_t)(row + 8) * DIM + col) =
                            __floats2half2_rn(acc[mi][nt][2] + b0, acc[mi][nt][3] + b1);
                }
            }
        }
        __syncthreads();
    }
}

// ---------------- K2: gather pass (one warp per dst node, high occupancy) ------
__global__ __launch_bounds__(256)
void gather_kernel(int n) {
    int node = (blockIdx.x * blockDim.x + threadIdx.x) >> 5;
    int l = threadIdx.x & 31;
    if (node >= n) return;

    int bpref = g_bsum[node >> 10];
    int end = bpref + g_off[node];             // after destructive scatter: inclusive end
    int beg = end - g_deg[node];

    uint2 ku = __ldg(((const uint2*)g_kh) + (size_t)node * 32 + l);
    float2 k01 = __half22float2(*(const __half2*)&ku.x);
    float2 k23 = __half22float2(*(const __half2*)&ku.y);

    float a0 = 0.f, a1 = 0.f, a2 = 0.f, a3 = 0.f;
    float dsum = 0.f;

    for (int base = beg; base < end; base += 32) {
        int m = end - base;
        if (m > 32) m = 32;
        int sl = (base + l < end) ? __ldg(&g_esrc[base + l]) : 0;
        #pragma unroll 2
        for (int j = 0; j < m; j++) {
            int s = __shfl_sync(0xffffffffu, sl, j);
            uint2 qu = __ldg(((const uint2*)g_qh) + (size_t)s * 32 + l);
            uint2 vu = __ldg(((const uint2*)g_vh) + (size_t)s * 32 + l);
            float2 q01 = __half22float2(*(const __half2*)&qu.x);
            float2 q23 = __half22float2(*(const __half2*)&qu.y);
            float p = q01.x * k01.x + q01.y * k01.y +
                      q23.x * k23.x + q23.y * k23.y;
            p += __shfl_xor_sync(0xffffffffu, p, 1);
            p += __shfl_xor_sync(0xffffffffu, p, 2);
            float we = __expf(p * 0.25f);
            float2 v01 = __half22float2(*(const __half2*)&vu.x);
            float2 v23 = __half22float2(*(const __half2*)&vu.y);
            a0 = fmaf(we, v01.x, a0);
            a1 = fmaf(we, v01.y, a1);
            a2 = fmaf(we, v23.x, a2);
            a3 = fmaf(we, v23.y, a3);
            dsum += we;
        }
    }

    float4 o = {a0, a1, a2, a3};
    ((float4*)g_agg)[(size_t)node * 32 + l] = o;
    if ((l & 3) == 0)
        g_denom[(size_t)node * NHEADS + (l >> 2)] = dsum;
}

// ---------------- K3: output projection via mma.sync bf16 ----------------------
#define OS_AHI  2048
#define OS_ALO  (OS_AHI + 32768)
#define OS_WH   (OS_ALO + 32768)
#define OS_WL   (OS_WH + 32768)
#define OS_TOTAL (OS_WL + 32768)           // 133120 bytes

__global__ __launch_bounds__(512, 1)
void outproj_mma_kernel(const float* __restrict__ bo, float* __restrict__ out,
                        int n, int ntiles) {
    extern __shared__ char smem[];
    uint32_t sb = smem_u32(smem);
    int tid = threadIdx.x, wid = tid >> 5, lane = tid & 31;
    int wm = wid & 3, wn = wid >> 2;
    int g = lane >> 2, t = lane & 3;

    float* bias_s = (float*)smem;
    for (int i = tid; i < 128; i += 512) bias_s[i] = bo[i];

    for (int c = tid; c < 2048; c += 512) {
        int r = c >> 4, k8 = (c & 15) << 3;
        uint32_t off = toff(r, k8);
        int gi = (r * DIM + k8) >> 3;
        *(uint4*)(smem + OS_WH + off) = ((const uint4*)g_Woh)[gi];
        *(uint4*)(smem + OS_WL + off) = ((const uint4*)g_Wol)[gi];
    }

    float xr[4][8];
    float dnr[4];
    auto load_tile = [&](int tt) {
        int r0n = tt << 7;
        #pragma unroll
        for (int i = 0; i < 4; i++) {
            int c = tid + (i << 9);
            int r = c >> 4, k8 = (c & 15) << 3;
            int gr = r0n + r;
            if (gr < n) {
                float4 f0 = __ldg((const float4*)(g_agg + (size_t)gr * DIM + k8));
                float4 f1 = __ldg((const float4*)(g_agg + (size_t)gr * DIM + k8 + 4));
                xr[i][0] = f0.x; xr[i][1] = f0.y; xr[i][2] = f0.z; xr[i][3] = f0.w;
                xr[i][4] = f1.x; xr[i][5] = f1.y; xr[i][6] = f1.z; xr[i][7] = f1.w;
                dnr[i] = __ldg(&g_denom[(size_t)gr * NHEADS + (k8 >> 4)]);
            } else {
                #pragma unroll
                for (int j = 0; j < 8; j++) xr[i][j] = 0.0f;
                dnr[i] = 0.0f;
            }
        }
    };
    if (blockIdx.x < ntiles) load_tile(blockIdx.x);
    __syncthreads();

    for (int tile = blockIdx.x; tile < ntiles; tile += gridDim.x) {
        int r0 = tile << 7;

        #pragma unroll
        for (int i = 0; i < 4; i++) {
            int c = tid + (i << 9);
            int r = c >> 4, k8 = (c & 15) << 3;
            float inv = (dnr[i] > 0.0f) ? __frcp_rn(dnr[i]) : 0.0f;
            float x[8];
            #pragma unroll
            for (int j = 0; j < 8; j++) x[j] = xr[i][j] * inv;
            uint4 uh, ul;
            split8(x, uh, ul);
            uint32_t off = toff(r, k8);
            *(uint4*)(smem + OS_AHI + off) = uh;
            *(uint4*)(smem + OS_ALO + off) = ul;
        }
        __syncthreads();

        int tn = tile + gridDim.x;
        if (tn < ntiles) load_tile(tn);

        float acc[2][4][4] = {};
        gemm128<true, true>(sb, OS_AHI, OS_ALO, OS_WH, OS_WL, acc, wm, wn, lane);

        #pragma unroll
        for (int mi = 0; mi < 2; mi++) {
            #pragma unroll
            for (int nt = 0; nt < 4; nt++) {
                int col = wn * 32 + nt * 8 + 2 * t;
                float b0 = bias_s[col], b1 = bias_s[col + 1];
                int row = r0 + wm * 32 + mi * 16 + g;
                if (row < n) {
                    float2 f = {acc[mi][nt][0] + b0, acc[mi][nt][1] + b1};
                    *(float2*)(out + (size_t)row * DIM + col) = f;
                }
                if (row + 8 < n) {
                    float2 f = {acc[mi][nt][2] + b0, acc[mi][nt][3] + b1};
                    *(float2*)(out + (size_t)(row + 8) * DIM + col) = f;
                }
            }
        }
        __syncthreads();
    }
}

// ---------------- launch -------------------------------------------------------
extern "C" void kernel_launch(void* const* d_in, const int* in_sizes, int n_in,
                              void* d_out, int out_size) {
    const float* h   = (const float*)d_in[0];
    const int*   src = (const int*)d_in[1];
    const int*   dst = (const int*)d_in[2];
    const float* Wq  = (const float*)d_in[3];
    const float* bq  = (const float*)d_in[4];
    const float* Wk  = (const float*)d_in[5];
    const float* bk  = (const float*)d_in[6];
    const float* Wv  = (const float*)d_in[7];
    const float* bv  = (const float*)d_in[8];
    const float* Wo  = (const float*)d_in[9];
    const float* bo  = (const float*)d_in[10];
    float* out = (float*)d_out;

    int n = in_sizes[0] / DIM;
    int E = in_sizes[1];
    int ntiles = (n + 127) / 128;

    cudaFuncSetAttribute(qkv_mma_kernel,
                         cudaFuncAttributeMaxDynamicSharedMemorySize, QS_TOTAL);
    cudaFuncSetAttribute(outproj_mma_kernel,
                         cudaFuncAttributeMaxDynamicSharedMemorySize, OS_TOTAL);

    setup_kernel<<<(NPAD + 255) / 256, 256>>>(Wq, Wk, Wv, Wo);

    qkv_mma_kernel<<<148, 512, QS_TOTAL>>>(h, bq, bk, bv, dst, E, n, ntiles);

    scanA_kernel<<<NPAD / 1024, 1024>>>();
    scanB_kernel<<<1, 64>>>();
    scatter_kernel<<<(E + 255) / 256, 256>>>(src, dst, E);

    gather_kernel<<<(n * 32 + 255) / 256, 256>>>(n);

    outproj_mma_kernel<<<148, 512, OS_TOTAL>>>(bo, out, n, ntiles);
}

// round 17
// speedup vs baseline: 1.9729x; 1.1092x over previous
#include <cuda_runtime.h>
#include <cuda_bf16.h>
#include <cuda_fp16.h>
#include <cstdint>

// Problem constants (shapes fixed by the dataset)
#define NMAX 50048
#define NPAD 50176                 // 49 * 1024, for the block scan
#define EMAX 800000
#define DIM  128
#define NHEADS 8
#define HDIM 16

// ---------------- scratch (device globals; no allocation allowed) -------------
// qv interleaved: per node 256 halfs; lane l owns halfs [8l..8l+7] =
// {q dims 4l..4l+3, v dims 4l..4l+3}  -> one uint4 per lane per edge in gather.
__device__ __half  g_qvh[NMAX * 256];
__device__ __half  g_kh[NMAX * DIM];
__device__ float   g_agg[NMAX * DIM];
__device__ float   g_denom[NMAX * NHEADS];
// CSR-by-dst build
__device__ int g_deg[NPAD];
__device__ int g_off[NPAD];        // within-block exclusive offsets (scanA); += deg after scatter
__device__ int g_bsum[64];         // per-scan-block global base (claimed via g_gctr)
__device__ int g_gctr;
__device__ int g_esrc[EMAX];
// bf16 weights (hi / lo split for the precision-critical paths)
__device__ __nv_bfloat16 g_Wqh[DIM * DIM];
__device__ __nv_bfloat16 g_Wkh[DIM * DIM];
__device__ __nv_bfloat16 g_Wvh[DIM * DIM];
__device__ __nv_bfloat16 g_Wvl[DIM * DIM];
__device__ __nv_bfloat16 g_Woh[DIM * DIM];
__device__ __nv_bfloat16 g_Wol[DIM * DIM];

// ---------------- helpers ------------------------------------------------------
__device__ __forceinline__ uint32_t smem_u32(const void* p) {
    uint32_t a;
    asm("{ .reg .u64 t; cvta.to.shared.u64 t, %1; cvt.u32.u64 %0, t; }"
        : "=r"(a) : "l"(p));
    return a;
}

// Swizzled byte offset in a [128 rows x 128 bf16] tile (XOR-16B-chunk swizzle).
__device__ __forceinline__ uint32_t toff(int r, int k) {
    return (uint32_t)((r << 8) + ((((k >> 3) ^ (r & 7))) << 4) + ((k & 7) << 1));
}

__device__ __forceinline__ void ldsm4(uint32_t addr, uint32_t* r) {
    asm volatile("ldmatrix.sync.aligned.m8n8.x4.shared.b16 {%0,%1,%2,%3}, [%4];"
                 : "=r"(r[0]), "=r"(r[1]), "=r"(r[2]), "=r"(r[3]) : "r"(addr));
}

__device__ __forceinline__ void mma16816(float* c, const uint32_t* a,
                                         const uint32_t* b) {
    asm volatile(
        "mma.sync.aligned.m16n8k16.row.col.f32.bf16.bf16.f32 "
        "{%0,%1,%2,%3}, {%4,%5,%6,%7}, {%8,%9}, {%0,%1,%2,%3};"
        : "+f"(c[0]), "+f"(c[1]), "+f"(c[2]), "+f"(c[3])
        : "r"(a[0]), "r"(a[1]), "r"(a[2]), "r"(a[3]), "r"(b[0]), "r"(b[1]));
}

__device__ __forceinline__ void split8(const float* x, uint4& uh, uint4& ul) {
    __nv_bfloat162* ph = (__nv_bfloat162*)&uh;
    __nv_bfloat162* pl = (__nv_bfloat162*)&ul;
    #pragma unroll
    for (int i = 0; i < 4; i++) {
        __nv_bfloat16 h0 = __float2bfloat16(x[2 * i]);
        __nv_bfloat16 h1 = __float2bfloat16(x[2 * i + 1]);
        ph[i] = __halves2bfloat162(h0, h1);
        pl[i] = __floats2bfloat162_rn(x[2 * i]     - __bfloat162float(h0),
                                      x[2 * i + 1] - __bfloat162float(h1));
    }
}

// 128x128x128 GEMM tile: acc += Ahi*Bhi (+ Alo*Bhi if ALO) (+ Ahi*Blo if BLO).
template <bool ALO, bool BLO>
__device__ __forceinline__ void gemm128(uint32_t sb, int a_hi, int a_lo,
                                        int b_hi, int b_lo,
                                        float acc[2][4][4],
                                        int wm, int wn, int lane) {
    int a_row = (lane & 7) + ((lane >> 3) & 1) * 8;
    int a_k   = ((lane >> 4) & 1) * 8;
    int b_row = ((lane >> 4) & 1) * 8 + (lane & 7);
    int b_k   = ((lane >> 3) & 1) * 8;

    #pragma unroll 1
    for (int k0 = 0; k0 < 8; k0++) {
        int kb = k0 * 16;
        uint32_t ah[2][4], al[2][4];
        #pragma unroll
        for (int mi = 0; mi < 2; mi++) {
            int row = wm * 32 + mi * 16 + a_row;
            ldsm4(sb + a_hi + toff(row, kb + a_k), ah[mi]);
            if (ALO) ldsm4(sb + a_lo + toff(row, kb + a_k), al[mi]);
        }
        uint32_t bh[2][4], bl[2][4];
        #pragma unroll
        for (int pr = 0; pr < 2; pr++) {
            int row = wn * 32 + pr * 16 + b_row;
            ldsm4(sb + b_hi + toff(row, kb + b_k), bh[pr]);
            if (BLO) ldsm4(sb + b_lo + toff(row, kb + b_k), bl[pr]);
        }
        #pragma unroll
        for (int mi = 0; mi < 2; mi++) {
            #pragma unroll
            for (int nt = 0; nt < 4; nt++) {
                uint32_t* b = &bh[nt >> 1][(nt & 1) * 2];
                mma16816(acc[mi][nt], ah[mi], b);
                if (ALO) mma16816(acc[mi][nt], al[mi], b);
                if (BLO) mma16816(acc[mi][nt], ah[mi], &bl[nt >> 1][(nt & 1) * 2]);
            }
        }
    }
}

// ---------------- K0: setup (zero deg + weight prep fused) ---------------------
__global__ void setup_kernel(const float* __restrict__ Wq, const float* __restrict__ Wk,
                             const float* __restrict__ Wv, const float* __restrict__ Wo) {
    int i = blockIdx.x * blockDim.x + threadIdx.x;
    if (i == 0) g_gctr = 0;
    if (i < NPAD) g_deg[i] = 0;
    if (i < DIM * DIM) {
        g_Wqh[i] = __float2bfloat16(Wq[i]);
        g_Wkh[i] = __float2bfloat16(Wk[i]);
        float v = Wv[i];
        __nv_bfloat16 vh = __float2bfloat16(v);
        g_Wvh[i] = vh;
        g_Wvl[i] = __float2bfloat16(v - __bfloat162float(vh));
        float o = Wo[i];
        __nv_bfloat16 oh = __float2bfloat16(o);
        g_Woh[i] = oh;
        g_Wol[i] = __float2bfloat16(o - __bfloat162float(oh));
    }
}

// ---------------- scanA: block scan + atomic block-base claim -------------------
__global__ void scanA_kernel() {               // 49 blocks x 1024
    __shared__ int wsum[32];
    int t = threadIdx.x;
    int lane = t & 31, w = t >> 5;
    int i = blockIdx.x * 1024 + t;
    int v = g_deg[i];
    int x = v;
    #pragma unroll
    for (int ofs = 1; ofs < 32; ofs <<= 1) {
        int y = __shfl_up_sync(0xffffffffu, x, ofs);
        if (lane >= ofs) x += y;
    }
    if (lane == 31) wsum[w] = x;
    __syncthreads();
    if (w == 0) {
        int s = wsum[lane];
        #pragma unroll
        for (int ofs = 1; ofs < 32; ofs <<= 1) {
            int y = __shfl_up_sync(0xffffffffu, s, ofs);
            if (lane >= ofs) s += y;
        }
        wsum[lane] = s;
    }
    __syncthreads();
    int bp = (w > 0) ? wsum[w - 1] : 0;
    g_off[i] = bp + x - v;                     // exclusive WITHIN block
    if (t == 1023)                             // claim global base (arrival order)
        g_bsum[blockIdx.x] = atomicAdd(&g_gctr, bp + x);
}

// Destructive scatter: global pos = block base + within-block running offset.
__global__ void scatter_kernel(const int* __restrict__ src,
                               const int* __restrict__ dst, int E) {
    int e = blockIdx.x * blockDim.x + threadIdx.x;
    if (e < E) {
        int d = dst[e];
        int pos = g_bsum[d >> 10] + atomicAdd(&g_off[d], 1);
        g_esrc[pos] = src[e];
    }
}

// ---------------- K1: QKV projection via mma.sync bf16 (+ fused histogram) -----
#define QS_AHI  2048
#define QS_ALO  (QS_AHI + 32768)
#define QS_WQ   (QS_ALO + 32768)
#define QS_WK   (QS_WQ + 32768)
#define QS_WVH  (QS_WK + 32768)
#define QS_WVL  (QS_WVH + 32768)
#define QS_TOTAL (QS_WVL + 32768)          // 198656 bytes

__global__ __launch_bounds__(512, 1)
void qkv_mma_kernel(const float* __restrict__ h,
                    const float* __restrict__ bq, const float* __restrict__ bk,
                    const float* __restrict__ bv,
                    const int* __restrict__ dst, int E, int n, int ntiles) {
    extern __shared__ char smem[];
    uint32_t sb = smem_u32(smem);
    int tid = threadIdx.x, wid = tid >> 5, lane = tid & 31;
    int wm = wid & 3, wn = wid >> 2;
    int g = lane >> 2, t = lane & 3;

    float* bias_s = (float*)smem;
    for (int i = tid; i < 384; i += 512)
        bias_s[i] = (i < 128) ? bq[i] : (i < 256) ? bk[i - 128] : bv[i - 256];

    for (int c = tid; c < 2048; c += 512) {
        int r = c >> 4, k8 = (c & 15) << 3;
        uint32_t off = toff(r, k8);
        int gi = (r * DIM + k8) >> 3;
        *(uint4*)(smem + QS_WQ  + off) = ((const uint4*)g_Wqh)[gi];
        *(uint4*)(smem + QS_WK  + off) = ((const uint4*)g_Wkh)[gi];
        *(uint4*)(smem + QS_WVH + off) = ((const uint4*)g_Wvh)[gi];
        *(uint4*)(smem + QS_WVL + off) = ((const uint4*)g_Wvl)[gi];
    }

    // fused degree histogram (g_deg zeroed by setup_kernel)
    for (int e = blockIdx.x * 512 + tid; e < E; e += gridDim.x * 512)
        atomicAdd(&g_deg[dst[e]], 1);

    float xr[4][8];
    auto load_tile = [&](int tt) {
        int r0n = tt << 7;
        #pragma unroll
        for (int i = 0; i < 4; i++) {
            int c = tid + (i << 9);
            int r = c >> 4, k8 = (c & 15) << 3;
            int gr = r0n + r;
            if (gr < n) {
                float4 f0 = __ldg((const float4*)(h + (size_t)gr * DIM + k8));
                float4 f1 = __ldg((const float4*)(h + (size_t)gr * DIM + k8 + 4));
                xr[i][0] = f0.x; xr[i][1] = f0.y; xr[i][2] = f0.z; xr[i][3] = f0.w;
                xr[i][4] = f1.x; xr[i][5] = f1.y; xr[i][6] = f1.z; xr[i][7] = f1.w;
            } else {
                #pragma unroll
                for (int j = 0; j < 8; j++) xr[i][j] = 0.0f;
            }
        }
    };
    if (blockIdx.x < ntiles) load_tile(blockIdx.x);
    __syncthreads();

    for (int tile = blockIdx.x; tile < ntiles; tile += gridDim.x) {
        int r0 = tile << 7;

        #pragma unroll
        for (int i = 0; i < 4; i++) {
            int c = tid + (i << 9);
            int r = c >> 4, k8 = (c & 15) << 3;
            uint4 uh, ul;
            split8(xr[i], uh, ul);
            uint32_t off = toff(r, k8);
            *(uint4*)(smem + QS_AHI + off) = uh;
            *(uint4*)(smem + QS_ALO + off) = ul;
        }
        __syncthreads();

        int tn = tile + gridDim.x;
        if (tn < ntiles) load_tile(tn);        // hides under the GEMMs below

        // ---- q (1 pass) -> interleaved qv slot 0..3 ----
        {
            float acc[2][4][4] = {};
            gemm128<false, false>(sb, QS_AHI, QS_ALO, QS_WQ, 0, acc, wm, wn, lane);
            #pragma unroll
            for (int mi = 0; mi < 2; mi++) {
                #pragma unroll
                for (int nt = 0; nt < 4; nt++) {
                    int col = wn * 32 + nt * 8 + 2 * t;
                    int slot = ((col >> 2) << 3) + (col & 3);      // q half-pos
                    float b0 = bias_s[col], b1 = bias_s[col + 1];
                    int row = r0 + wm * 32 + mi * 16 + g;
                    if (row < n)
                        *(__half2*)(g_qvh + (size_t)row * 256 + slot) =
                            __floats2half2_rn(acc[mi][nt][0] + b0, acc[mi][nt][1] + b1);
                    if (row + 8 < n)
                        *(__half2*)(g_qvh + (size_t)(row + 8) * 256 + slot) =
                            __floats2half2_rn(acc[mi][nt][2] + b0, acc[mi][nt][3] + b1);
                }
            }
        }
        // ---- k (1 pass) ----
        {
            float acc[2][4][4] = {};
            gemm128<false, false>(sb, QS_AHI, QS_ALO, QS_WK, 0, acc, wm, wn, lane);
            #pragma unroll
            for (int mi = 0; mi < 2; mi++) {
                #pragma unroll
                for (int nt = 0; nt < 4; nt++) {
                    int col = wn * 32 + nt * 8 + 2 * t;
                    float b0 = bias_s[128 + col], b1 = bias_s[128 + col + 1];
                    int row = r0 + wm * 32 + mi * 16 + g;
                    if (row < n)
                        *(__half2*)(g_kh + (size_t)row * DIM + col) =
                            __floats2half2_rn(acc[mi][nt][0] + b0, acc[mi][nt][1] + b1);
                    if (row + 8 < n)
                        *(__half2*)(g_kh + (size_t)(row + 8) * DIM + col) =
                            __floats2half2_rn(acc[mi][nt][2] + b0, acc[mi][nt][3] + b1);
                }
            }
        }
        // ---- v (3-pass split) -> interleaved qv slot 4..7 ----
        {
            float acc[2][4][4] = {};
            gemm128<true, true>(sb, QS_AHI, QS_ALO, QS_WVH, QS_WVL, acc, wm, wn, lane);
            #pragma unroll
            for (int mi = 0; mi < 2; mi++) {
                #pragma unroll
                for (int nt = 0; nt < 4; nt++) {
                    int col = wn * 32 + nt * 8 + 2 * t;
                    int slot = ((col >> 2) << 3) + (col & 3) + 4;  // v half-pos
                    float b0 = bias_s[256 + col], b1 = bias_s[256 + col + 1];
                    int row = r0 + wm * 32 + mi * 16 + g;
                    if (row < n)
                        *(__half2*)(g_qvh + (size_t)row * 256 + slot) =
                            __floats2half2_rn(acc[mi][nt][0] + b0, acc[mi][nt][1] + b1);
                    if (row + 8 < n)
                        *(__half2*)(g_qvh + (size_t)(row + 8) * 256 + slot) =
                            __floats2half2_rn(acc[mi][nt][2] + b0, acc[mi][nt][3] + b1);
                }
            }
        }
        __syncthreads();
    }
}

// ---------------- K2: gather (one warp per dst node, 4-edge pipeline) ----------
__device__ __forceinline__ void edge_accum(uint4 u, float2 k01, float2 k23,
                                           float& a0, float& a1, float& a2,
                                           float& a3, float& dsum) {
    float2 q01 = __half22float2(*(const __half2*)&u.x);
    float2 q23 = __half22float2(*(const __half2*)&u.y);
    float p = q01.x * k01.x + q01.y * k01.y + q23.x * k23.x + q23.y * k23.y;
    p += __shfl_xor_sync(0xffffffffu, p, 1);
    p += __shfl_xor_sync(0xffffffffu, p, 2);
    float we = __expf(p * 0.25f);
    float2 v01 = __half22float2(*(const __half2*)&u.z);
    float2 v23 = __half22float2(*(const __half2*)&u.w);
    a0 = fmaf(we, v01.x, a0);
    a1 = fmaf(we, v01.y, a1);
    a2 = fmaf(we, v23.x, a2);
    a3 = fmaf(we, v23.y, a3);
    dsum += we;
}

__global__ __launch_bounds__(256)
void gather_kernel(int n) {
    int node = (blockIdx.x * blockDim.x + threadIdx.x) >> 5;
    int l = threadIdx.x & 31;
    if (node >= n) return;

    int end = g_bsum[node >> 10] + g_off[node]; // after destructive scatter
    int beg = end - g_deg[node];

    uint2 ku = __ldg(((const uint2*)g_kh) + (size_t)node * 32 + l);
    float2 k01 = __half22float2(*(const __half2*)&ku.x);
    float2 k23 = __half22float2(*(const __half2*)&ku.y);

    float a0 = 0.f, a1 = 0.f, a2 = 0.f, a3 = 0.f;
    float dsum = 0.f;
    const uint4* qv = (const uint4*)g_qvh;

    for (int base = beg; base < end; base += 32) {
        int m = end - base;
        if (m >= 32) {
            int sl = __ldg(&g_esrc[base + l]);
            #pragma unroll
            for (int jb = 0; jb < 32; jb += 4) {
                int s0 = __shfl_sync(0xffffffffu, sl, jb);
                int s1 = __shfl_sync(0xffffffffu, sl, jb + 1);
                int s2 = __shfl_sync(0xffffffffu, sl, jb + 2);
                int s3 = __shfl_sync(0xffffffffu, sl, jb + 3);
                uint4 u0 = __ldg(qv + (size_t)s0 * 32 + l);
                uint4 u1 = __ldg(qv + (size_t)s1 * 32 + l);
                uint4 u2 = __ldg(qv + (size_t)s2 * 32 + l);
                uint4 u3 = __ldg(qv + (size_t)s3 * 32 + l);
                edge_accum(u0, k01, k23, a0, a1, a2, a3, dsum);
                edge_accum(u1, k01, k23, a0, a1, a2, a3, dsum);
                edge_accum(u2, k01, k23, a0, a1, a2, a3, dsum);
                edge_accum(u3, k01, k23, a0, a1, a2, a3, dsum);
            }
        } else {
            int sl = (base + l < end) ? __ldg(&g_esrc[base + l]) : 0;
            for (int j = 0; j < m; j++) {
                int s = __shfl_sync(0xffffffffu, sl, j);
                uint4 u = __ldg(qv + (size_t)s * 32 + l);
                edge_accum(u, k01, k23, a0, a1, a2, a3, dsum);
            }
        }
    }

    float4 o = {a0, a1, a2, a3};
    ((float4*)g_agg)[(size_t)node * 32 + l] = o;
    if ((l & 3) == 0)
        g_denom[(size_t)node * NHEADS + (l >> 2)] = dsum;
}

// ---------------- K3: output projection via mma.sync bf16 ----------------------
#define OS_AHI  2048
#define OS_ALO  (OS_AHI + 32768)
#define OS_WH   (OS_ALO + 32768)
#define OS_WL   (OS_WH + 32768)
#define OS_TOTAL (OS_WL + 32768)           // 133120 bytes

__global__ __launch_bounds__(512, 1)
void outproj_mma_kernel(const float* __restrict__ bo, float* __restrict__ out,
                        int n, int ntiles) {
    extern __shared__ char smem[];
    uint32_t sb = smem_u32(smem);
    int tid = threadIdx.x, wid = tid >> 5, lane = tid & 31;
    int wm = wid & 3, wn = wid >> 2;
    int g = lane >> 2, t = lane & 3;

    float* bias_s = (float*)smem;
    for (int i = tid; i < 128; i += 512) bias_s[i] = bo[i];

    for (int c = tid; c < 2048; c += 512) {
        int r = c >> 4, k8 = (c & 15) << 3;
        uint32_t off = toff(r, k8);
        int gi = (r * DIM + k8) >> 3;
        *(uint4*)(smem + OS_WH + off) = ((const uint4*)g_Woh)[gi];
        *(uint4*)(smem + OS_WL + off) = ((const uint4*)g_Wol)[gi];
    }

    float xr[4][8];
    float dnr[4];
    auto load_tile = [&](int tt) {
        int r0n = tt << 7;
        #pragma unroll
        for (int i = 0; i < 4; i++) {
            int c = tid + (i << 9);
            int r = c >> 4, k8 = (c & 15) << 3;
            int gr = r0n + r;
            if (gr < n) {
                float4 f0 = __ldg((const float4*)(g_agg + (size_t)gr * DIM + k8));
                float4 f1 = __ldg((const float4*)(g_agg + (size_t)gr * DIM + k8 + 4));
                xr[i][0] = f0.x; xr[i][1] = f0.y; xr[i][2] = f0.z; xr[i][3] = f0.w;
                xr[i][4] = f1.x; xr[i][5] = f1.y; xr[i][6] = f1.z; xr[i][7] = f1.w;
                dnr[i] = __ldg(&g_denom[(size_t)gr * NHEADS + (k8 >> 4)]);
            } else {
                #pragma unroll
                for (int j = 0; j < 8; j++) xr[i][j] = 0.0f;
                dnr[i] = 0.0f;
            }
        }
    };
    if (blockIdx.x < ntiles) load_tile(blockIdx.x);
    __syncthreads();

    for (int tile = blockIdx.x; tile < ntiles; tile += gridDim.x) {
        int r0 = tile << 7;

        #pragma unroll
        for (int i = 0; i < 4; i++) {
            int c = tid + (i << 9);
            int r = c >> 4, k8 = (c & 15) << 3;
            float inv = (dnr[i] > 0.0f) ? __frcp_rn(dnr[i]) : 0.0f;
            float x[8];
            #pragma unroll
            for (int j = 0; j < 8; j++) x[j] = xr[i][j] * inv;
            uint4 uh, ul;
            split8(x, uh, ul);
            uint32_t off = toff(r, k8);
            *(uint4*)(smem + OS_AHI + off) = uh;
            *(uint4*)(smem + OS_ALO + off) = ul;
        }
        __syncthreads();

        int tn = tile + gridDim.x;
        if (tn < ntiles) load_tile(tn);

        float acc[2][4][4] = {};
        gemm128<true, true>(sb, OS_AHI, OS_ALO, OS_WH, OS_WL, acc, wm, wn, lane);

        #pragma unroll
        for (int mi = 0; mi < 2; mi++) {
            #pragma unroll
            for (int nt = 0; nt < 4; nt++) {
                int col = wn * 32 + nt * 8 + 2 * t;
                float b0 = bias_s[col], b1 = bias_s[col + 1];
                int row = r0 + wm * 32 + mi * 16 + g;
                if (row < n) {
                    float2 f = {acc[mi][nt][0] + b0, acc[mi][nt][1] + b1};
                    *(float2*)(out + (size_t)row * DIM + col) = f;
                }
                if (row + 8 < n) {
                    float2 f = {acc[mi][nt][2] + b0, acc[mi][nt][3] + b1};
                    *(float2*)(out + (size_t)(row + 8) * DIM + col) = f;
                }
            }
        }
        __syncthreads();
    }
}

// ---------------- launch -------------------------------------------------------
extern "C" void kernel_launch(void* const* d_in, const int* in_sizes, int n_in,
                              void* d_out, int out_size) {
    const float* h   = (const float*)d_in[0];
    const int*   src = (const int*)d_in[1];
    const int*   dst = (const int*)d_in[2];
    const float* Wq  = (const float*)d_in[3];
    const float* bq  = (const float*)d_in[4];
    const float* Wk  = (const float*)d_in[5];
    const float* bk  = (const float*)d_in[6];
    const float* Wv  = (const float*)d_in[7];
    const float* bv  = (const float*)d_in[8];
    const float* Wo  = (const float*)d_in[9];
    const float* bo  = (const float*)d_in[10];
    float* out = (float*)d_out;

    int n = in_sizes[0] / DIM;
    int E = in_sizes[1];
    int ntiles = (n + 127) / 128;

    cudaFuncSetAttribute(qkv_mma_kernel,
                         cudaFuncAttributeMaxDynamicSharedMemorySize, QS_TOTAL);
    cudaFuncSetAttribute(outproj_mma_kernel,
                         cudaFuncAttributeMaxDynamicSharedMemorySize, OS_TOTAL);

    setup_kernel<<<(NPAD + 255) / 256, 256>>>(Wq, Wk, Wv, Wo);

    qkv_mma_kernel<<<148, 512, QS_TOTAL>>>(h, bq, bk, bv, dst, E, n, ntiles);

    scanA_kernel<<<NPAD / 1024, 1024>>>();
    scatter_kernel<<<(E + 255) / 256, 256>>>(src, dst, E);

    gather_kernel<<<(n * 32 + 255) / 256, 256>>>(n);

    outproj_mma_kernel<<<148, 512, OS_TOTAL>>>(bo, out, n, ntiles);
}